// round 3
// baseline (speedup 1.0000x reference)
#include <cuda_runtime.h>
#include <cstdint>

#define N_NODE   100000
#define NROWS    102000       // N_NODE + N_ATTRI
#define NFEAT    256
#define NDIM     128
#define BM       128          // rows per GEMM block
#define BK       16           // K chunk
#define GEMM_THREADS 256

// Transposed weights: g_Wt[k*128 + c] = W1[c*256 + k]
__device__ float g_Wt[NFEAT * NDIM];

__global__ void transpose_W_kernel(const float* __restrict__ W1) {
    int idx = blockIdx.x * blockDim.x + threadIdx.x;
    if (idx < NFEAT * NDIM) {
        int k = idx >> 7;     // / 128
        int c = idx & 127;
        g_Wt[idx] = W1[c * NFEAT + k];
    }
}

// x1 = x0 @ W1^T.  x0 row r comes from embN (r<N_NODE) or embA.
// Also zeroes this block's x2/x3 rows (SpMM accumulates into them later).
__global__ __launch_bounds__(GEMM_THREADS)
void gemm_kernel(const float* __restrict__ embN, const float* __restrict__ embA,
                 float* __restrict__ x1, float* __restrict__ x2, float* __restrict__ x3) {
    __shared__ float As[BK][BM];        // k-major:  As[k][row]   (8 KB)
    __shared__ float Bs[BK][NDIM];      // Bs[k][col]             (8 KB)

    const int t    = threadIdx.x;
    const int row0 = blockIdx.x * BM;
    const int tx   = t & 15;            // 16 col-groups of 8 cols
    const int ty   = t >> 4;            // 16 row-groups of 8 rows

    // Zero this block's x2/x3 rows
    {
        float4 z = make_float4(0.f, 0.f, 0.f, 0.f);
        for (int idx = t; idx < BM * 32; idx += GEMM_THREADS) {
            int r = row0 + (idx >> 5);
            if (r < NROWS) {
                ((float4*)x2)[(size_t)r * 32 + (idx & 31)] = z;
                ((float4*)x3)[(size_t)r * 32 + (idx & 31)] = z;
            }
        }
    }

    float acc[8][8];
    #pragma unroll
    for (int i = 0; i < 8; i++)
        #pragma unroll
        for (int j = 0; j < 8; j++) acc[i][j] = 0.f;

    // A-load mapping: 128 rows x 16 k per chunk = 2048 floats = 512 float4;
    // each thread loads 2 float4 along k of one row pair.
    const int a_row = t >> 1;                 // 0..127
    const int a_k4  = (t & 1) * 2;            // float4 index within 16-k chunk: 0 or 2
    // B-load mapping: 16 k x 128 c = 2048 floats; thread loads 2 float4 coalesced.
    const int b_k   = t >> 3;                 // 0..31 -> two k via +? (16k only) use t>>4
    (void)b_k;

    for (int kc = 0; kc < NFEAT; kc += BK) {
        __syncthreads();
        // Load A chunk: rows row0..row0+127, k = kc..kc+15
        {
            int gr = row0 + a_row;
            float4 v0 = make_float4(0.f,0.f,0.f,0.f), v1 = v0;
            if (gr < NROWS) {
                const float* src = (gr < N_NODE)
                    ? (embN + (size_t)gr * NFEAT)
                    : (embA + (size_t)(gr - N_NODE) * NFEAT);
                v0 = *(const float4*)(src + kc + a_k4 * 4);
                v1 = *(const float4*)(src + kc + a_k4 * 4 + 4);
            }
            int k0 = a_k4 * 4;
            As[k0 + 0][a_row] = v0.x; As[k0 + 1][a_row] = v0.y;
            As[k0 + 2][a_row] = v0.z; As[k0 + 3][a_row] = v0.w;
            As[k0 + 4][a_row] = v1.x; As[k0 + 5][a_row] = v1.y;
            As[k0 + 6][a_row] = v1.z; As[k0 + 7][a_row] = v1.w;
        }
        // Load B chunk: Bs[k][c] = g_Wt[(kc+k)*128 + c], coalesced float4
        {
            const float4* wg = (const float4*)(g_Wt + (size_t)kc * NDIM);
            float4* bs4 = (float4*)&Bs[0][0];
            bs4[t]                = wg[t];
            bs4[t + GEMM_THREADS] = wg[t + GEMM_THREADS];
        }
        __syncthreads();

        #pragma unroll
        for (int k = 0; k < BK; k++) {
            float a[8], b[8];
            #pragma unroll
            for (int i = 0; i < 4; i++) {
                ((float2*)a)[i]     = *(const float2*)&As[k][ty * 8 + i * 2];
                ((float2*)b)[i]     = *(const float2*)&Bs[k][tx * 8 + i * 2];
            }
            #pragma unroll
            for (int i = 0; i < 8; i++)
                #pragma unroll
                for (int j = 0; j < 8; j++)
                    acc[i][j] = fmaf(a[i], b[j], acc[i][j]);
        }
    }

    // Store 8x8 micro-tile, float4-coalesced
    #pragma unroll
    for (int i = 0; i < 8; i++) {
        int gr = row0 + ty * 8 + i;
        if (gr < NROWS) {
            float4* dst = (float4*)(x1 + (size_t)gr * NDIM + tx * 8);
            dst[0] = make_float4(acc[i][0], acc[i][1], acc[i][2], acc[i][3]);
            dst[1] = make_float4(acc[i][4], acc[i][5], acc[i][6], acc[i][7]);
        }
    }
}

// Warp-per-edge SpMM: out[row] += val * x1[col], float4 atomics (RED.128, no return path).
__global__ void spmm_kernel(const int* __restrict__ row, const int* __restrict__ col,
                            const float* __restrict__ val, const float* __restrict__ x1,
                            float* __restrict__ out, int nedges) {
    int wid = (blockIdx.x * blockDim.x + threadIdx.x) >> 5;
    if (wid >= nedges) return;
    int   lane = threadIdx.x & 31;
    int   r = __ldg(row + wid);
    int   c = __ldg(col + wid);
    float v = __ldg(val + wid);
    float4 a = ((const float4*)x1)[(size_t)c * 32 + lane];
    a.x *= v; a.y *= v; a.z *= v; a.w *= v;
    atomicAdd((float4*)(out + (size_t)r * NDIM + lane * 4), a);
}

extern "C" void kernel_launch(void* const* d_in, const int* in_sizes, int n_in,
                              void* d_out, int out_size) {
    const float* embN = (const float*)d_in[0];
    const float* embA = (const float*)d_in[1];
    const float* W1   = (const float*)d_in[2];
    const int*   a1r  = (const int*)d_in[3];
    const int*   a1c  = (const int*)d_in[4];
    const float* a1v  = (const float*)d_in[5];
    const int*   a2r  = (const int*)d_in[6];
    const int*   a2c  = (const int*)d_in[7];
    const float* a2v  = (const float*)d_in[8];

    float* out = (float*)d_out;
    float* x1 = out;
    float* x2 = out +     (size_t)NROWS * NDIM;
    float* x3 = out + 2 * (size_t)NROWS * NDIM;
    int E1 = in_sizes[3];
    int E2 = in_sizes[6];

    transpose_W_kernel<<<(NFEAT * NDIM + 255) / 256, 256>>>(W1);
    gemm_kernel<<<(NROWS + BM - 1) / BM, GEMM_THREADS>>>(embN, embA, x1, x2, x3);
    {
        long long th1 = (long long)E1 * 32;
        spmm_kernel<<<(unsigned)((th1 + 255) / 256), 256>>>(a1r, a1c, a1v, x1, x2, E1);
    }
    {
        long long th2 = (long long)E2 * 32;
        spmm_kernel<<<(unsigned)((th2 + 255) / 256), 256>>>(a2r, a2c, a2v, x1, x3, E2);
    }
}

// round 4
// speedup vs baseline: 1.0309x; 1.0309x over previous
#include <cuda_runtime.h>
#include <cstdint>

#define N_NODE   100000
#define NROWS    102000
#define NFEAT    256
#define NDIM     128
#define BM       128
#define BK       16
#define GEMM_THREADS 256

__device__ float g_Wt[NFEAT * NDIM];   // g_Wt[k*128 + c] = W1[c*256 + k]

__global__ void transpose_W_kernel(const float* __restrict__ W1) {
    int idx = blockIdx.x * blockDim.x + threadIdx.x;
    if (idx < NFEAT * NDIM) {
        int k = idx >> 7, c = idx & 127;
        g_Wt[idx] = W1[c * NFEAT + k];
    }
}

__device__ __forceinline__ unsigned long long dupf(float f) {
    unsigned long long r;
    asm("mov.b64 %0, {%1, %1};" : "=l"(r) : "f"(f));
    return r;
}
__device__ __forceinline__ float2 unpk(unsigned long long v) {
    float2 r;
    asm("mov.b64 {%0, %1}, %2;" : "=f"(r.x), "=f"(r.y) : "l"(v));
    return r;
}
#define FMA2(acc, a, b) asm("fma.rn.f32x2 %0, %1, %2, %0;" : "+l"(acc) : "l"(a), "l"(b))

// x1 = x0 @ W1^T via packed f32x2 FMA. Also zeroes this block's x2/x3 rows.
// acc[p][j] packs rows (ty*8+2p, ty*8+2p+1) for column c_j in
// {2tx, 2tx+1, 2tx+32, 2tx+33, 2tx+64, 2tx+65, 2tx+96, 2tx+97}.
__global__ __launch_bounds__(GEMM_THREADS, 2)
void gemm_kernel(const float* __restrict__ embN, const float* __restrict__ embA,
                 float* __restrict__ x1, float* __restrict__ x2, float* __restrict__ x3) {
    __shared__ float As[BK][BM];                      // k-major, 8 KB
    __shared__ unsigned long long Bs2[BK][NDIM];      // duplicated {w,w}, 16 KB

    const int t    = threadIdx.x;
    const int tx   = t & 15;
    const int ty   = t >> 4;
    const int row0 = blockIdx.x * BM;

    // Zero this block's x2/x3 rows (SpMM atomics accumulate later)
    {
        float4 z = make_float4(0.f, 0.f, 0.f, 0.f);
        for (int idx = t; idx < BM * 32; idx += GEMM_THREADS) {
            int r = row0 + (idx >> 5);
            if (r < NROWS) {
                ((float4*)x2)[(size_t)r * 32 + (idx & 31)] = z;
                ((float4*)x3)[(size_t)r * 32 + (idx & 31)] = z;
            }
        }
    }

    unsigned long long acc[4][8];
    #pragma unroll
    for (int p = 0; p < 4; p++)
        #pragma unroll
        for (int j = 0; j < 8; j++) acc[p][j] = 0ULL;

    const int a_row = t >> 1;
    const int a_k4  = (t & 1) * 2;

    for (int kc = 0; kc < NFEAT; kc += BK) {
        __syncthreads();
        // A chunk: As[k][row], rows row0..row0+127, k = kc..kc+15
        {
            int gr = row0 + a_row;
            float4 v0 = make_float4(0.f, 0.f, 0.f, 0.f), v1 = v0;
            if (gr < NROWS) {
                const float* src = (gr < N_NODE)
                    ? (embN + (size_t)gr * NFEAT)
                    : (embA + (size_t)(gr - N_NODE) * NFEAT);
                v0 = *(const float4*)(src + kc + a_k4 * 4);
                v1 = *(const float4*)(src + kc + a_k4 * 4 + 4);
            }
            int k0 = a_k4 * 4;
            As[k0 + 0][a_row] = v0.x; As[k0 + 1][a_row] = v0.y;
            As[k0 + 2][a_row] = v0.z; As[k0 + 3][a_row] = v0.w;
            As[k0 + 4][a_row] = v1.x; As[k0 + 5][a_row] = v1.y;
            As[k0 + 6][a_row] = v1.z; As[k0 + 7][a_row] = v1.w;
        }
        // B chunk: Bs2[k][c] = dup(g_Wt[(kc+k)*128 + c])
        {
            const float4* wg = (const float4*)(g_Wt + (size_t)kc * NDIM);
            #pragma unroll
            for (int u = 0; u < 2; u++) {
                int idx = t + u * GEMM_THREADS;    // 0..511 float4s of the chunk
                int k   = idx >> 5;                // 32 float4 per k-row
                int c4  = idx & 31;
                float4 w = wg[idx];
                unsigned long long* dst = &Bs2[k][c4 * 4];
                dst[0] = dupf(w.x); dst[1] = dupf(w.y);
                dst[2] = dupf(w.z); dst[3] = dupf(w.w);
            }
        }
        __syncthreads();

        #pragma unroll
        for (int k = 0; k < BK; k++) {
            // row-pairs: {A[r0],A[r1]} packed naturally (consecutive floats)
            ulonglong2 a01 = *(const ulonglong2*)&As[k][ty * 8];
            ulonglong2 a23 = *(const ulonglong2*)&As[k][ty * 8 + 4];
            unsigned long long av0 = a01.x, av1 = a01.y, av2 = a23.x, av3 = a23.y;
            #pragma unroll
            for (int j = 0; j < 4; j++) {
                // two duplicated columns, lane-contiguous 16B (conflict-free)
                ulonglong2 b = *(const ulonglong2*)&Bs2[k][2 * tx + 32 * j];
                FMA2(acc[0][2 * j],     av0, b.x); FMA2(acc[0][2 * j + 1], av0, b.y);
                FMA2(acc[1][2 * j],     av1, b.x); FMA2(acc[1][2 * j + 1], av1, b.y);
                FMA2(acc[2][2 * j],     av2, b.x); FMA2(acc[2][2 * j + 1], av2, b.y);
                FMA2(acc[3][2 * j],     av3, b.x); FMA2(acc[3][2 * j + 1], av3, b.y);
            }
        }
    }

    // Store: per row-pair p, per column-pair jj, float2 stores (lane-contiguous 128B)
    #pragma unroll
    for (int p = 0; p < 4; p++) {
        int r0 = row0 + ty * 8 + 2 * p;
        if (r0 < NROWS) {   // NROWS even, r0 even => r0+1 also in range
            #pragma unroll
            for (int jj = 0; jj < 4; jj++) {
                float2 u0 = unpk(acc[p][2 * jj]);       // {row r0, row r0+1} col c
                float2 u1 = unpk(acc[p][2 * jj + 1]);   // col c+1
                *(float2*)(x1 + (size_t)r0 * NDIM + 2 * tx + 32 * jj)       = make_float2(u0.x, u1.x);
                *(float2*)(x1 + (size_t)(r0 + 1) * NDIM + 2 * tx + 32 * jj) = make_float2(u0.y, u1.y);
            }
        }
    }
}

// Half-feature SpMM: 16 threads per edge, 64 features (256B) per edge per pass.
// Working set per pass (x1 half + dst halves) is L2-resident.
__global__ void spmm_half_kernel(const int* __restrict__ row, const int* __restrict__ col,
                                 const float* __restrict__ val, const float* __restrict__ x1,
                                 float* __restrict__ out, int nedges, int foff) {
    int gt = blockIdx.x * blockDim.x + threadIdx.x;
    int e  = gt >> 4;
    if (e >= nedges) return;
    int   fl = gt & 15;
    int   r = __ldg(row + e);
    int   c = __ldg(col + e);
    float v = __ldg(val + e);
    float4 a = ((const float4*)(x1 + (size_t)c * NDIM + foff))[fl];
    a.x *= v; a.y *= v; a.z *= v; a.w *= v;
    atomicAdd(((float4*)(out + (size_t)r * NDIM + foff)) + fl, a);
}

extern "C" void kernel_launch(void* const* d_in, const int* in_sizes, int n_in,
                              void* d_out, int out_size) {
    const float* embN = (const float*)d_in[0];
    const float* embA = (const float*)d_in[1];
    const float* W1   = (const float*)d_in[2];
    const int*   a1r  = (const int*)d_in[3];
    const int*   a1c  = (const int*)d_in[4];
    const float* a1v  = (const float*)d_in[5];
    const int*   a2r  = (const int*)d_in[6];
    const int*   a2c  = (const int*)d_in[7];
    const float* a2v  = (const float*)d_in[8];

    float* out = (float*)d_out;
    float* x1 = out;
    float* x2 = out +     (size_t)NROWS * NDIM;
    float* x3 = out + 2 * (size_t)NROWS * NDIM;
    int E1 = in_sizes[3];
    int E2 = in_sizes[6];

    transpose_W_kernel<<<(NFEAT * NDIM + 255) / 256, 256>>>(W1);
    gemm_kernel<<<(NROWS + BM - 1) / BM, GEMM_THREADS>>>(embN, embA, x1, x2, x3);

    unsigned g1 = (unsigned)(((long long)E1 * 16 + 255) / 256);
    unsigned g2 = (unsigned)(((long long)E2 * 16 + 255) / 256);
    // half 0 for both adjacencies (shared x1-half L2 residency), then half 1
    spmm_half_kernel<<<g1, 256>>>(a1r, a1c, a1v, x1, x2, E1, 0);
    spmm_half_kernel<<<g2, 256>>>(a2r, a2c, a2v, x1, x3, E2, 0);
    spmm_half_kernel<<<g1, 256>>>(a1r, a1c, a1v, x1, x2, E1, 64);
    spmm_half_kernel<<<g2, 256>>>(a2r, a2c, a2v, x1, x3, E2, 64);
}

// round 5
// speedup vs baseline: 1.2088x; 1.1726x over previous
#include <cuda_runtime.h>
#include <cstdint>

#define N_NODE   100000
#define NROWS    102000
#define NFEAT    256
#define NDIM     128
#define BM       128
#define BK       16
#define GEMM_THREADS 256
#define EPW      8          // edges per warp in spmm (4 per thread-pair-group)

__device__ float g_Wt[NFEAT * NDIM];   // g_Wt[k*128 + c] = W1[c*256 + k]

__global__ void transpose_W_kernel(const float* __restrict__ W1) {
    int idx = blockIdx.x * blockDim.x + threadIdx.x;
    if (idx < NFEAT * NDIM) {
        int k = idx >> 7, c = idx & 127;
        g_Wt[idx] = W1[c * NFEAT + k];
    }
}

__device__ __forceinline__ unsigned long long dupf(float f) {
    unsigned long long r;
    asm("mov.b64 %0, {%1, %1};" : "=l"(r) : "f"(f));
    return r;
}
__device__ __forceinline__ float2 unpk(unsigned long long v) {
    float2 r;
    asm("mov.b64 {%0, %1}, %2;" : "=f"(r.x), "=f"(r.y) : "l"(v));
    return r;
}
#define FMA2(acc, a, b) asm("fma.rn.f32x2 %0, %1, %2, %0;" : "+l"(acc) : "l"(a), "l"(b))

// x1 = x0 @ W1^T via packed f32x2 FMA. Also zeroes this block's x2/x3 rows.
__global__ __launch_bounds__(GEMM_THREADS, 2)
void gemm_kernel(const float* __restrict__ embN, const float* __restrict__ embA,
                 float* __restrict__ x1, float* __restrict__ x2, float* __restrict__ x3) {
    __shared__ float As[BK][BM];                      // k-major, 8 KB
    __shared__ unsigned long long Bs2[BK][NDIM];      // duplicated {w,w}, 16 KB

    const int t    = threadIdx.x;
    const int tx   = t & 15;
    const int ty   = t >> 4;
    const int row0 = blockIdx.x * BM;

    {
        float4 z = make_float4(0.f, 0.f, 0.f, 0.f);
        for (int idx = t; idx < BM * 32; idx += GEMM_THREADS) {
            int r = row0 + (idx >> 5);
            if (r < NROWS) {
                ((float4*)x2)[(size_t)r * 32 + (idx & 31)] = z;
                ((float4*)x3)[(size_t)r * 32 + (idx & 31)] = z;
            }
        }
    }

    unsigned long long acc[4][8];
    #pragma unroll
    for (int p = 0; p < 4; p++)
        #pragma unroll
        for (int j = 0; j < 8; j++) acc[p][j] = 0ULL;

    const int a_row = t >> 1;
    const int a_k4  = (t & 1) * 2;

    for (int kc = 0; kc < NFEAT; kc += BK) {
        __syncthreads();
        {
            int gr = row0 + a_row;
            float4 v0 = make_float4(0.f, 0.f, 0.f, 0.f), v1 = v0;
            if (gr < NROWS) {
                const float* src = (gr < N_NODE)
                    ? (embN + (size_t)gr * NFEAT)
                    : (embA + (size_t)(gr - N_NODE) * NFEAT);
                v0 = *(const float4*)(src + kc + a_k4 * 4);
                v1 = *(const float4*)(src + kc + a_k4 * 4 + 4);
            }
            int k0 = a_k4 * 4;
            As[k0 + 0][a_row] = v0.x; As[k0 + 1][a_row] = v0.y;
            As[k0 + 2][a_row] = v0.z; As[k0 + 3][a_row] = v0.w;
            As[k0 + 4][a_row] = v1.x; As[k0 + 5][a_row] = v1.y;
            As[k0 + 6][a_row] = v1.z; As[k0 + 7][a_row] = v1.w;
        }
        {
            const float4* wg = (const float4*)(g_Wt + (size_t)kc * NDIM);
            #pragma unroll
            for (int u = 0; u < 2; u++) {
                int idx = t + u * GEMM_THREADS;
                int k   = idx >> 5;
                int c4  = idx & 31;
                float4 w = wg[idx];
                unsigned long long* dst = &Bs2[k][c4 * 4];
                dst[0] = dupf(w.x); dst[1] = dupf(w.y);
                dst[2] = dupf(w.z); dst[3] = dupf(w.w);
            }
        }
        __syncthreads();

        #pragma unroll
        for (int k = 0; k < BK; k++) {
            ulonglong2 a01 = *(const ulonglong2*)&As[k][ty * 8];
            ulonglong2 a23 = *(const ulonglong2*)&As[k][ty * 8 + 4];
            unsigned long long av0 = a01.x, av1 = a01.y, av2 = a23.x, av3 = a23.y;
            #pragma unroll
            for (int j = 0; j < 4; j++) {
                ulonglong2 b = *(const ulonglong2*)&Bs2[k][2 * tx + 32 * j];
                FMA2(acc[0][2 * j],     av0, b.x); FMA2(acc[0][2 * j + 1], av0, b.y);
                FMA2(acc[1][2 * j],     av1, b.x); FMA2(acc[1][2 * j + 1], av1, b.y);
                FMA2(acc[2][2 * j],     av2, b.x); FMA2(acc[2][2 * j + 1], av2, b.y);
                FMA2(acc[3][2 * j],     av3, b.x); FMA2(acc[3][2 * j + 1], av3, b.y);
            }
        }
    }

    #pragma unroll
    for (int p = 0; p < 4; p++) {
        int r0 = row0 + ty * 8 + 2 * p;
        if (r0 < NROWS) {
            #pragma unroll
            for (int jj = 0; jj < 4; jj++) {
                float2 u0 = unpk(acc[p][2 * jj]);
                float2 u1 = unpk(acc[p][2 * jj + 1]);
                *(float2*)(x1 + (size_t)r0 * NDIM + 2 * tx + 32 * jj)       = make_float2(u0.x, u1.x);
                *(float2*)(x1 + (size_t)(r0 + 1) * NDIM + 2 * tx + 32 * jj) = make_float2(u0.y, u1.y);
            }
        }
    }
}

// Half-feature SpMM with 4 edges per thread (MLP=4).
// Warp owns EPW=8 edges; lane's half-warp (sub) picks edge 2*i+sub per iter;
// fl = lane&15 covers 64 features as float4. All 4 gathers are issued before
// any RED so LDGs front-batch in the L1tex queue.
__global__ void __launch_bounds__(256)
spmm_half4_kernel(const int* __restrict__ row, const int* __restrict__ col,
                  const float* __restrict__ val, const float* __restrict__ x1,
                  float* __restrict__ out, int nedges, int foff) {
    int wid  = (blockIdx.x * blockDim.x + threadIdx.x) >> 5;
    int lane = threadIdx.x & 31;
    int sub  = lane >> 4;          // 0/1: which edge of the pair
    int fl   = lane & 15;          // float4 index within 64-feature half
    int e0   = wid * EPW;
    if (e0 >= nedges) return;

    const float4* x1h = (const float4*)(x1 + foff);

    if (e0 + EPW <= nedges) {
        int   r[4], c[4];
        float v[4];
        #pragma unroll
        for (int i = 0; i < 4; i++) {
            int e = e0 + 2 * i + sub;
            r[i] = __ldg(row + e);
            c[i] = __ldg(col + e);
            v[i] = __ldg(val + e);
        }
        float4 a[4];
        #pragma unroll
        for (int i = 0; i < 4; i++)
            a[i] = x1h[(size_t)c[i] * 32 + fl];      // 4 independent gathers in flight
        #pragma unroll
        for (int i = 0; i < 4; i++) {
            a[i].x *= v[i]; a[i].y *= v[i]; a[i].z *= v[i]; a[i].w *= v[i];
            atomicAdd(((float4*)(out + (size_t)r[i] * NDIM + foff)) + fl, a[i]);
        }
    } else {
        for (int i = 0; i < 4; i++) {
            int e = e0 + 2 * i + sub;
            if (e < nedges) {
                int   rr = __ldg(row + e);
                int   cc = __ldg(col + e);
                float vv = __ldg(val + e);
                float4 a = x1h[(size_t)cc * 32 + fl];
                a.x *= vv; a.y *= vv; a.z *= vv; a.w *= vv;
                atomicAdd(((float4*)(out + (size_t)rr * NDIM + foff)) + fl, a);
            }
        }
    }
}

extern "C" void kernel_launch(void* const* d_in, const int* in_sizes, int n_in,
                              void* d_out, int out_size) {
    const float* embN = (const float*)d_in[0];
    const float* embA = (const float*)d_in[1];
    const float* W1   = (const float*)d_in[2];
    const int*   a1r  = (const int*)d_in[3];
    const int*   a1c  = (const int*)d_in[4];
    const float* a1v  = (const float*)d_in[5];
    const int*   a2r  = (const int*)d_in[6];
    const int*   a2c  = (const int*)d_in[7];
    const float* a2v  = (const float*)d_in[8];

    float* out = (float*)d_out;
    float* x1 = out;
    float* x2 = out +     (size_t)NROWS * NDIM;
    float* x3 = out + 2 * (size_t)NROWS * NDIM;
    int E1 = in_sizes[3];
    int E2 = in_sizes[6];

    transpose_W_kernel<<<(NFEAT * NDIM + 255) / 256, 256>>>(W1);
    gemm_kernel<<<(NROWS + BM - 1) / BM, GEMM_THREADS>>>(embN, embA, x1, x2, x3);

    auto nwarps = [](int E) { return (E + EPW - 1) / EPW; };
    unsigned g1 = (unsigned)(((long long)nwarps(E1) * 32 + 255) / 256);
    unsigned g2 = (unsigned)(((long long)nwarps(E2) * 32 + 255) / 256);
    // half 0 for both adjacencies (shared x1-half L2 residency), then half 1
    spmm_half4_kernel<<<g1, 256>>>(a1r, a1c, a1v, x1, x2, E1, 0);
    spmm_half4_kernel<<<g2, 256>>>(a2r, a2c, a2v, x1, x3, E2, 0);
    spmm_half4_kernel<<<g1, 256>>>(a1r, a1c, a1v, x1, x2, E1, 64);
    spmm_half4_kernel<<<g2, 256>>>(a2r, a2c, a2v, x1, x3, E2, 64);
}